// round 3
// baseline (speedup 1.0000x reference)
#include <cuda_runtime.h>
#include <cuda_bf16.h>

// RFFT2d: x (32,1,1024,1024) f32 -> 8x8 blocks -> rfft(len 8) along block cols
// -> out (32, 16384, 8, 5, 2) f32, scaled by 1/64.
//
// One CTA per (n, bh) slab: 8 rows x 1024 cols input (8192 floats, contiguous),
// producing 1024 signals x 10 floats output (10240 floats, contiguous).
// Stage outputs in smem (stride 11 per signal -> conflict-free STS), then
// stream out fully coalesced float4 stores.

#define THREADS 256
#define SLAB_IN   8192   // floats per slab input
#define SLAB_OUT 10240   // floats per slab output
#define STAGE_WORDS 11264  // 1024*11 + 2 (max addr 11262)

__global__ void __launch_bounds__(THREADS)
rfft2d_kernel(const float* __restrict__ x, float* __restrict__ out)
{
    __shared__ float stage[STAGE_WORDS];

    const int slab = blockIdx.x;               // slab = n*128 + bh
    const float* __restrict__ in = x + (size_t)slab * SLAB_IN;
    float* __restrict__ o = out + (size_t)slab * SLAB_OUT;

    const int t   = threadIdx.x;
    const int r   = t & 7;        // block row  (0..7)
    const int bw0 = t >> 3;       // base block col (0..31)

    const float c = 0.70710678118654752440f;   // cos(pi/4)
    const float s = 1.0f / 64.0f;

    // ---- compute phase: 4 signals per thread ----
#pragma unroll
    for (int q = 0; q < 4; q++) {
        const int bw = bw0 + 32 * q;           // 0..127
        const float4* p = (const float4*)(in + r * 1024 + bw * 8);
        const float4 lo = p[0];
        const float4 hi = p[1];

        // radix-2 decomposition
        const float a0 = lo.x + hi.x, a1 = lo.y + hi.y;
        const float a2 = lo.z + hi.z, a3 = lo.w + hi.w;
        const float b0 = lo.x - hi.x, b1 = lo.y - hi.y;
        const float b2 = lo.z - hi.z, b3 = lo.w - hi.w;

        const float e0 = a0 + a2, e1 = a1 + a3;   // DC / Nyquist
        const float d0 = a0 - a2, d1 = a1 - a3;   // k=2
        const float u  = c * (b1 - b3);           // k=1,3 twiddles
        const float v  = c * (b1 + b3);

        // X[k] = sum x[n] e^{-2pi i kn/8};  out = [Re,Im]/64
        const float re0 = (e0 + e1) * s;
        const float re1 = (b0 + u) * s,  im1 = -(b2 + v) * s;
        const float re2 =  d0 * s,       im2 = -d1 * s;
        const float re3 = (b0 - u) * s,  im3 =  (b2 - v) * s;
        const float re4 = (e0 - e1) * s;

        // stage at signal stride 11 (odd -> conflict-free scalar STS for
        // the warp's (r 0..7 x bw 0..3) lane layout)
        float* st = &stage[(bw * 8 + r) * 11];
        st[0] = re0;  st[1] = 0.0f;
        st[2] = re1;  st[3] = im1;
        st[4] = re2;  st[5] = im2;
        st[6] = re3;  st[7] = im3;
        st[8] = re4;  st[9] = 0.0f;
    }

    __syncthreads();

    // ---- unload phase: 10240 floats = 2560 float4, fully coalesced ----
    // gmem word o maps to smem word (o + o/10)  [since stride 11 = 10 + 1]
#pragma unroll
    for (int w = 0; w < 10; w++) {
        const int idx4 = t + THREADS * w;      // 0..2559
        const int ob = idx4 * 4;
        float4 v4;
        v4.x = stage[(ob + 0) + (ob + 0) / 10];
        v4.y = stage[(ob + 1) + (ob + 1) / 10];
        v4.z = stage[(ob + 2) + (ob + 2) / 10];
        v4.w = stage[(ob + 3) + (ob + 3) / 10];
        ((float4*)o)[idx4] = v4;
    }
}

extern "C" void kernel_launch(void* const* d_in, const int* in_sizes, int n_in,
                              void* d_out, int out_size)
{
    const float* x = (const float*)d_in[0];
    float* out = (float*)d_out;
    const int nslabs = in_sizes[0] / SLAB_IN;   // 32*128 = 4096
    rfft2d_kernel<<<nslabs, THREADS>>>(x, out);
}

// round 4
// speedup vs baseline: 1.5096x; 1.5096x over previous
#include <cuda_runtime.h>
#include <cuda_bf16.h>

// RFFT2d: x (32,1,1024,1024) f32 -> 8x8 blocks -> rfft(len 8) along rows of
// blocks -> out (32, 16384, 8, 5, 2) f32 scaled by 1/64.
//
// One CTA per HALF-slab: 8 rows x 512 cols of input (rows strided 1024),
// 512 signals x 10 output floats (contiguous 20 KB out region).
//
// Load phase: fully coalesced 128B-line LDG.128 (rows 0-3 then 4-7 of a
// 128B column group), then one shfl_xor(1) pair-exchange reassembles each
// signal's 8 floats in a single lane. Warp signal set = {r 0..7 x bw 0..3}
// -> stride-11 smem staging is bank-conflict-free (scalar STS).
// Drain: fully coalesced float4 STG via word map o -> o + o/10.

#define THREADS 256

__global__ void __launch_bounds__(THREADS, 6)
rfft2d_kernel(const float* __restrict__ x, float* __restrict__ out)
{
    __shared__ float stage[5640];              // 512*11 + pad (max addr 5630)

    const int hs   = blockIdx.x;               // half-slab id (0..8191)
    const int slab = hs >> 1;
    const int half = hs & 1;
    const float* __restrict__ in = x + (size_t)slab * 8192 + half * 512;
    float* __restrict__ o = out + (size_t)slab * 10240 + half * 5120;

    const int t    = threadIdx.x;
    const int w    = t >> 5;                   // warp 0..7
    const int lane = t & 31;
    const int a    = lane >> 3;                // row base 0..3
    const int ch   = lane & 7;                 // 16B chunk in 128B group
    const int bwl  = ch >> 1;                  // block col within group (0..3)
    const int h    = lane & 1;                 // half-of-signal this lane loaded

    const float c = 0.70710678118654752440f;   // cos(pi/4)
    const float s = 1.0f / 64.0f;

#pragma unroll
    for (int q = 0; q < 2; q++) {
        const int g = q * 8 + w;               // column group 0..15 (128B each)
        const float* base = in + a * 1024 + g * 32 + ch * 4;
        const float4 Q1 = *(const float4*)base;             // rows 0..3
        const float4 Q2 = *(const float4*)(base + 4 * 1024); // rows 4..7

        // pair exchange: lane i <-> i^1 swap the "other half" float4s
        float4 P1, P2;
        P1.x = __shfl_xor_sync(0xffffffffu, Q1.x, 1);
        P1.y = __shfl_xor_sync(0xffffffffu, Q1.y, 1);
        P1.z = __shfl_xor_sync(0xffffffffu, Q1.z, 1);
        P1.w = __shfl_xor_sync(0xffffffffu, Q1.w, 1);
        P2.x = __shfl_xor_sync(0xffffffffu, Q2.x, 1);
        P2.y = __shfl_xor_sync(0xffffffffu, Q2.y, 1);
        P2.z = __shfl_xor_sync(0xffffffffu, Q2.z, 1);
        P2.w = __shfl_xor_sync(0xffffffffu, Q2.w, 1);

        // even lane (h=0): signal (row a,   bw) : lo=Q1, hi=P1
        // odd  lane (h=1): signal (row a+4, bw) : lo=P2, hi=Q2
        const float4 lo = h ? P2 : Q1;
        const float4 hi = h ? Q2 : P1;
        const int r   = a + 4 * h;
        const int sig = (g * 4 + bwl) * 8 + r;  // 0..511 local

        // length-8 real FFT
        const float a0 = lo.x + hi.x, a1 = lo.y + hi.y;
        const float a2 = lo.z + hi.z, a3 = lo.w + hi.w;
        const float b0 = lo.x - hi.x, b1 = lo.y - hi.y;
        const float b2 = lo.z - hi.z, b3 = lo.w - hi.w;

        const float e0 = a0 + a2, e1 = a1 + a3;
        const float d0 = a0 - a2, d1 = a1 - a3;
        const float u  = c * (b1 - b3);
        const float v  = c * (b1 + b3);

        const float re0 = (e0 + e1) * s;
        const float re1 = (b0 + u) * s,  im1 = -(b2 + v) * s;
        const float re2 =  d0 * s,       im2 = -d1 * s;
        const float re3 = (b0 - u) * s,  im3 =  (b2 - v) * s;
        const float re4 = (e0 - e1) * s;

        float* st = &stage[sig * 11];           // conflict-free scalar STS
        st[0] = re0;  st[1] = 0.0f;
        st[2] = re1;  st[3] = im1;
        st[4] = re2;  st[5] = im2;
        st[6] = re3;  st[7] = im3;
        st[8] = re4;  st[9] = 0.0f;
    }

    __syncthreads();

    // drain: 5120 floats = 1280 float4, fully coalesced STG.128
    // gmem word o -> smem word o + o/10  (stride 11 = 10 + 1)
#pragma unroll
    for (int k = 0; k < 5; k++) {
        const int idx4 = t + THREADS * k;       // 0..1279
        const int ob = idx4 * 4;
        float4 v4;
        v4.x = stage[(ob + 0) + (ob + 0) / 10];
        v4.y = stage[(ob + 1) + (ob + 1) / 10];
        v4.z = stage[(ob + 2) + (ob + 2) / 10];
        v4.w = stage[(ob + 3) + (ob + 3) / 10];
        ((float4*)o)[idx4] = v4;
    }
}

extern "C" void kernel_launch(void* const* d_in, const int* in_sizes, int n_in,
                              void* d_out, int out_size)
{
    const float* x = (const float*)d_in[0];
    float* out = (float*)d_out;
    const int nhalf = in_sizes[0] / 4096;       // 8192 half-slabs
    rfft2d_kernel<<<nhalf, THREADS>>>(x, out);
}